// round 4
// baseline (speedup 1.0000x reference)
#include <cuda_runtime.h>
#include <math.h>

#define NB   8
#define DC   32
#define HS   512
#define WSZ  512
#define HH   256
#define WW   256
#define KW   7
#define KK2  49
#define HID  64
#define AA   256
#define NPIX 65536   // HH*WW

typedef unsigned long long ull;

// ---------------- scratch (device globals; no runtime alloc) ----------------
__device__ float g_x  [NB * DC  * NPIX];   // pooled input x
__device__ float g_h1 [NB * HID * NPIX];   // h after conv_in / h3
__device__ float g_h2 [NB * HID * NPIX];   // h after dil-3 conv
__device__ float g_u  [NB * KK2 * NPIX];   // exp(z - m)  (unnormalized probs)
__device__ float g_sc [NB * NPIX];         // exp(log_belief)/s per pixel
__device__ float g_lang[NB * KK2];

// packed weights (pre-transposed once per launch)
__device__ ull g_w3[HID * 9 * 32];   // dil3 conv: [ic][tap][ocpair]
__device__ ull g_w1[HID * 9 * 32];   // dil1 conv
__device__ ull g_wi[DC * 32];        // conv_in:  [c][ocpair]
__device__ ull g_wo[HID * 16];       // w_out:    [ic][cpair]
__device__ ull g_wk[DC * 25];        // w_k:      [c][kkpair] (pad kk=49 with 0)

// ---------------- f32x2 helpers ------------------------------------------
__device__ __forceinline__ ull pack2(float lo, float hi) {
    ull r; asm("mov.b64 %0, {%1, %2};" : "=l"(r) : "f"(lo), "f"(hi)); return r;
}
__device__ __forceinline__ void unpack2(ull v, float& lo, float& hi) {
    asm("mov.b64 {%0, %1}, %2;" : "=f"(lo), "=f"(hi) : "l"(v));
}
__device__ __forceinline__ void ffma2(ull& d, ull a, ull b) {
    asm("fma.rn.f32x2 %0, %1, %2, %0;" : "+l"(d) : "l"(a), "l"(b));
}

// fast exp on the FMA pipe (no MUFU): exp(x) = 2^(x*log2e), poly deg-5
__device__ __forceinline__ float fexp(float x) {
    float t  = fmaxf(x * 1.44269504f, -120.f);
    float rv = rintf(t);
    int   e  = (int)rv;
    float f  = t - rv;
    float p  = 1.33335581e-3f;
    p = fmaf(p, f, 9.61812910e-3f);
    p = fmaf(p, f, 5.55041087e-2f);
    p = fmaf(p, f, 2.40226507e-1f);
    p = fmaf(p, f, 6.93147181e-1f);
    p = fmaf(p, f, 1.0f);
    return __int_as_float(__float_as_int(p) + (e << 23));
}

// ---------------- K0: pre-pack all weights --------------------------------
__global__ void k_prepw(const float* __restrict__ w_d3, const float* __restrict__ w_d1,
                        const float* __restrict__ w_in, const float* __restrict__ w_out,
                        const float* __restrict__ w_k) {
    int i = blockIdx.x * 256 + threadIdx.x;
    if (i < 18432) {
        int j = i & 31, t = i >> 5, tap = t % 9, ic = t / 9;
        g_w3[i] = pack2(w_d3[((2*j)*HID + ic)*9 + tap], w_d3[((2*j+1)*HID + ic)*9 + tap]);
    } else if (i < 36864) {
        int q = i - 18432;
        int j = q & 31, t = q >> 5, tap = t % 9, ic = t / 9;
        g_w1[q] = pack2(w_d1[((2*j)*HID + ic)*9 + tap], w_d1[((2*j+1)*HID + ic)*9 + tap]);
    } else if (i < 37888) {
        int q = i - 36864; int c = q >> 5, j = q & 31;
        g_wi[q] = pack2(w_in[(2*j)*DC + c], w_in[(2*j+1)*DC + c]);
    } else if (i < 38912) {
        int q = i - 37888; int ic = q >> 4, cc = q & 15;
        g_wo[q] = pack2(w_out[(2*cc)*HID + ic], w_out[(2*cc+1)*HID + ic]);
    } else if (i < 39712) {
        int q = i - 38912; int c = q / 25, kk = q % 25;
        float w1v = (2*kk + 1 < KK2) ? w_k[(2*kk+1)*DC + c] : 0.f;
        g_wk[q] = pack2(w_k[(2*kk)*DC + c], w1v);
    }
}

// ---------------- K1: 2x2 max pool ----------------------------------------
__global__ void k_maxpool(const float* __restrict__ sem) {
    int idx = blockIdx.x * blockDim.x + threadIdx.x;   // over NB*DC*NPIX
    int x  = idx & (WW - 1);
    int y  = (idx >> 8) & (HH - 1);
    int nc = idx >> 16;
    const float* base = sem + (size_t)nc * HS * WSZ;
    const float2* r0 = (const float2*)(base + (size_t)(2 * y)     * WSZ);
    const float2* r1 = (const float2*)(base + (size_t)(2 * y + 1) * WSZ);
    float2 a = r0[x];
    float2 b = r1[x];
    g_x[idx] = fmaxf(fmaxf(a.x, a.y), fmaxf(b.x, b.y));
}

// ---------------- K2: conv1x1 32->64 + relu (f32x2) ------------------------
__global__ __launch_bounds__(256) void k_conv_in(const float* __restrict__ b) {
    __shared__ ull   sw2[DC * 32];
    __shared__ float sb[HID];
    for (int i = threadIdx.x; i < DC * 32; i += 256) sw2[i] = g_wi[i];
    if (threadIdx.x < HID) sb[threadIdx.x] = b[threadIdx.x];
    __syncthreads();

    int p   = blockIdx.x * 256 + threadIdx.x;
    int n   = p >> 16;
    int pix = p & (NPIX - 1);

    ull acc[32];
#pragma unroll
    for (int j = 0; j < 32; j++) acc[j] = pack2(sb[2*j], sb[2*j+1]);

    const float* xb = g_x + (size_t)n * DC * NPIX + pix;
#pragma unroll
    for (int c = 0; c < DC; c++) {
        float xv = xb[(size_t)c * NPIX];
        ull xp = pack2(xv, xv);
#pragma unroll
        for (int j = 0; j < 32; j++) ffma2(acc[j], sw2[c*32 + j], xp);
    }
    float* ob = g_h1 + (size_t)n * HID * NPIX + pix;
#pragma unroll
    for (int j = 0; j < 32; j++) {
        float lo, hi; unpack2(acc[j], lo, hi);
        ob[(size_t)(2*j  ) * NPIX] = fmaxf(lo, 0.f);
        ob[(size_t)(2*j+1) * NPIX] = fmaxf(hi, 0.f);
    }
}

// ---------------- K3/K4: conv3x3 (dilated) 64->64 + relu (f32x2) -----------
template <int DIL, bool H1toH2>
__global__ __launch_bounds__(256, 2) void k_conv3x3(const ull* __restrict__ wp,
                                                    const float* __restrict__ bg) {
    constexpr int TX = 32, TY = 8, ICS = 16;
    constexpr int ROWS = TY + 2 * DIL;
    constexpr int COLS = TX + 2 * DIL;

    const float* in  = H1toH2 ? g_h1 : g_h2;
    float*       out = H1toH2 ? g_h2 : g_h1;

    extern __shared__ float smem[];
    float* s_in = smem;                                 // [ICS][ROWS][COLS]
    ull*   s_w  = (ull*)(smem + ICS * ROWS * COLS);     // [ICS][9][32] oc-pairs

    int tid  = threadIdx.x;
    int lane = tid & 31;
    int ogrp = tid >> 5;
    int bx = blockIdx.x * TX;
    int by = blockIdx.y * TY;
    int n  = blockIdx.z;
    const float* inb = in + (size_t)n * HID * NPIX;

    ull acc[4][TY];
#pragma unroll
    for (int o = 0; o < 4; o++)
#pragma unroll
        for (int yy = 0; yy < TY; yy++) acc[o][yy] = 0ull;

    for (int ic0 = 0; ic0 < HID; ic0 += ICS) {
        __syncthreads();
        // stage input tile (zero-padded halo)
        for (int i = tid; i < ICS * ROWS * COLS; i += 256) {
            int col = i % COLS;
            int t   = i / COLS;
            int row = t % ROWS;
            int ic  = t / ROWS;
            int gy = by + row - DIL;
            int gx = bx + col - DIL;
            float v = 0.f;
            if (gy >= 0 && gy < HH && gx >= 0 && gx < WW)
                v = inb[(size_t)(ic0 + ic) * NPIX + gy * WW + gx];
            s_in[i] = v;
        }
        // stage packed weight chunk: coalesced copy
        const ull* wsrc = wp + (size_t)ic0 * 9 * 32;
        for (int i = tid; i < ICS * 9 * 32; i += 256) s_w[i] = wsrc[i];
        __syncthreads();

        for (int ic = 0; ic < ICS; ic++) {
            const float* si  = s_in + ic * ROWS * COLS + lane;
            const ull*   swc = s_w + ic * 9 * 32 + ogrp * 4;
#pragma unroll
            for (int ky = 0; ky < 3; ky++) {
#pragma unroll
                for (int kx = 0; kx < 3; kx++) {
                    ull xp[TY];
#pragma unroll
                    for (int yy = 0; yy < TY; yy++) {
                        float xv = si[(yy + ky * DIL) * COLS + kx * DIL];
                        xp[yy] = pack2(xv, xv);
                    }
                    ull w2[4];
#pragma unroll
                    for (int o = 0; o < 4; o++) w2[o] = swc[(ky*3 + kx) * 32 + o];
#pragma unroll
                    for (int o = 0; o < 4; o++)
#pragma unroll
                        for (int yy = 0; yy < TY; yy++) ffma2(acc[o][yy], w2[o], xp[yy]);
                }
            }
        }
    }

    float* ob = out + (size_t)n * HID * NPIX + (size_t)by * WW + bx + lane;
#pragma unroll
    for (int o = 0; o < 4; o++) {
        int oc = ogrp * 8 + 2 * o;
        float b0 = __ldg(&bg[oc]);
        float b1 = __ldg(&bg[oc + 1]);
#pragma unroll
        for (int yy = 0; yy < TY; yy++) {
            float lo, hi; unpack2(acc[o][yy], lo, hi);
            ob[(size_t)oc       * NPIX + yy * WW] = fmaxf(lo + b0, 0.f);
            ob[(size_t)(oc + 1) * NPIX + yy * WW] = fmaxf(hi + b1, 0.f);
        }
    }
}

// ---------------- K5: lang = log_softmax(relu(a@w1+b1)@w2+b2) -------------
__global__ void k_lang(const float* __restrict__ act,
                       const float* __restrict__ w1, const float* __restrict__ b1,
                       const float* __restrict__ w2, const float* __restrict__ b2) {
    int n = blockIdx.x;
    int t = threadIdx.x;      // 64 threads
    __shared__ float sh[HID];
    __shared__ float sz[KK2];
    __shared__ float slse;

    float acc = b1[t];
    for (int i = 0; i < AA; i++) acc = fmaf(act[n * AA + i], w1[i * HID + t], acc);
    sh[t] = fmaxf(acc, 0.f);
    __syncthreads();

    if (t < KK2) {
        float z = b2[t];
        for (int j = 0; j < HID; j++) z = fmaf(sh[j], w2[j * KK2 + t], z);
        sz[t] = z;
    }
    __syncthreads();
    if (t == 0) {
        float m = -1e30f;
        for (int k = 0; k < KK2; k++) m = fmaxf(m, sz[k]);
        float s = 0.f;
        for (int k = 0; k < KK2; k++) s += __expf(sz[k] - m);
        slse = m + __logf(s);
    }
    __syncthreads();
    if (t < KK2) g_lang[n * KK2 + t] = sz[t] - slse;
}

// ---- K6: fused  x2 = x + conv1x1(h3) ;  z = w_k*x2 + b_k + lang ;
//          u = exp(z - m) streamed, scale = exp(lb)/sum(u) -----------------
__global__ __launch_bounds__(256) void k_motion(const float* __restrict__ b_out,
                                                const float* __restrict__ b_k,
                                                const float* __restrict__ lb) {
    __shared__ ull   swo2[HID * 16];   // [ic][cpair]
    __shared__ ull   swk2[DC * 25];    // [c][kkpair]
    __shared__ float sbo[DC];
    __shared__ float sbk[KK2];
    for (int i = threadIdx.x; i < HID * 16; i += 256) swo2[i] = g_wo[i];
    for (int i = threadIdx.x; i < DC * 25;  i += 256) swk2[i] = g_wk[i];
    if (threadIdx.x < DC)  sbo[threadIdx.x] = b_out[threadIdx.x];
    if (threadIdx.x < KK2) sbk[threadIdx.x] = b_k[threadIdx.x];
    __syncthreads();

    int p   = blockIdx.x * 256 + threadIdx.x;
    int n   = p >> 16;
    int pix = p & (NPIX - 1);

    // x2 = x + b_out + W_out h3   (packed over channel pairs)
    ull x22[16];
    const float* xb = g_x + (size_t)n * DC * NPIX + pix;
#pragma unroll
    for (int cc = 0; cc < 16; cc++)
        x22[cc] = pack2(xb[(size_t)(2*cc)*NPIX]   + sbo[2*cc],
                        xb[(size_t)(2*cc+1)*NPIX] + sbo[2*cc+1]);

    const float* hb = g_h1 + (size_t)n * HID * NPIX + pix;   // h3 lives in g_h1
    for (int ic = 0; ic < HID; ic++) {
        float hv = hb[(size_t)ic * NPIX];
        ull hp = pack2(hv, hv);
#pragma unroll
        for (int cc = 0; cc < 16; cc++) ffma2(x22[cc], swo2[ic*16 + cc], hp);
    }

    // z = w_k x2 + b_k + lang   (packed over kk pairs; pad kk=49)
    const float* lg = g_lang + n * KK2;
    ull z2[25];
#pragma unroll
    for (int kk = 0; kk < 24; kk++)
        z2[kk] = pack2(sbk[2*kk]   + __ldg(&lg[2*kk]),
                       sbk[2*kk+1] + __ldg(&lg[2*kk+1]));
    z2[24] = pack2(sbk[48] + __ldg(&lg[48]), -1e4f);

#pragma unroll
    for (int cc = 0; cc < 16; cc++) {
        float x0, x1; unpack2(x22[cc], x0, x1);
        ull xp0 = pack2(x0, x0);
#pragma unroll
        for (int kk = 0; kk < 25; kk++) ffma2(z2[kk], swk2[(2*cc)*25 + kk], xp0);
        ull xp1 = pack2(x1, x1);
#pragma unroll
        for (int kk = 0; kk < 25; kk++) ffma2(z2[kk], swk2[(2*cc+1)*25 + kk], xp1);
    }

    float m = -1e30f;
#pragma unroll
    for (int kk = 0; kk < 25; kk++) {
        float a, b2v; unpack2(z2[kk], a, b2v);
        m = fmaxf(m, fmaxf(a, b2v));
    }

    float s = 0.f;
    float* ubp = g_u + (size_t)n * KK2 * NPIX + pix;
#pragma unroll
    for (int kk = 0; kk < 25; kk++) {
        float a, b2v; unpack2(z2[kk], a, b2v);
        float ua = fexp(a - m);
        s += ua;
        ubp[(size_t)(2*kk) * NPIX] = ua;
        if (kk < 24) {
            float ubv = fexp(b2v - m);
            s += ubv;
            ubp[(size_t)(2*kk+1) * NPIX] = ubv;
        }
    }
    g_sc[p] = __fdividef(fexp(lb[p]), s);
}

// ---------------- K7: gather logsumexp (exp domain, no MUFU exp) -----------
__global__ __launch_bounds__(256) void k_gather(float* __restrict__ out) {
    int p   = blockIdx.x * 256 + threadIdx.x;
    int n   = p >> 16;
    int pix = p & (NPIX - 1);
    int y = pix >> 8;
    int x = pix & (WW - 1);

    const float* ub = g_u  + (size_t)n * KK2 * NPIX;
    const float* sc = g_sc + (size_t)n * NPIX;
    float s = 0.f;
#pragma unroll
    for (int ki = 0; ki < KW; ki++) {
        int h = y - ki + 3;
        if (h < 0 || h >= HH) continue;
        int rb = h * WW;
#pragma unroll
        for (int kj = 0; kj < KW; kj++) {
            int w = x - kj + 3;
            if (w < 0 || w >= WW) continue;
            int kk = ki * KW + kj;
            s = fmaf(ub[(size_t)kk * NPIX + rb + w], sc[rb + w], s);
        }
    }
    out[p] = __logf(s);
}

// ---------------- launch ---------------------------------------------------
extern "C" void kernel_launch(void* const* d_in, const int* in_sizes, int n_in,
                              void* d_out, int out_size) {
    const float* log_belief = (const float*)d_in[0];
    const float* semantic   = (const float*)d_in[1];
    const float* action     = (const float*)d_in[2];
    const float* w_in  = (const float*)d_in[3];
    const float* b_in  = (const float*)d_in[4];
    const float* w_d3  = (const float*)d_in[5];
    const float* b_d3  = (const float*)d_in[6];
    const float* w_d1  = (const float*)d_in[7];
    const float* b_d1  = (const float*)d_in[8];
    const float* w_out = (const float*)d_in[9];
    const float* b_out = (const float*)d_in[10];
    const float* w_k   = (const float*)d_in[11];
    const float* b_k   = (const float*)d_in[12];
    const float* w_a1  = (const float*)d_in[13];
    const float* b_a1  = (const float*)d_in[14];
    const float* w_a2  = (const float*)d_in[15];
    const float* b_a2  = (const float*)d_in[16];
    float* out = (float*)d_out;

    constexpr int SMEM3 = (16 * 14 * 38) * 4 + (16 * 9 * 32) * 8;   // 70912 B
    constexpr int SMEM1 = (16 * 10 * 34) * 4 + (16 * 9 * 32) * 8;   // 58624 B
    cudaFuncSetAttribute(k_conv3x3<3, true>,
                         cudaFuncAttributeMaxDynamicSharedMemorySize, SMEM3);
    cudaFuncSetAttribute(k_conv3x3<1, false>,
                         cudaFuncAttributeMaxDynamicSharedMemorySize, SMEM1);

    ull* w3p; cudaGetSymbolAddress((void**)&w3p, g_w3);
    ull* w1p; cudaGetSymbolAddress((void**)&w1p, g_w1);

    k_prepw<<<(39712 + 255) / 256, 256>>>(w_d3, w_d1, w_in, w_out, w_k);
    k_maxpool<<<(NB * DC * NPIX) / 256, 256>>>(semantic);
    k_conv_in<<<(NB * NPIX) / 256, 256>>>(b_in);

    dim3 cgrid(WW / 32, HH / 8, NB);
    k_conv3x3<3, true ><<<cgrid, 256, SMEM3>>>(w3p, b_d3);   // h1 -> h2
    k_conv3x3<1, false><<<cgrid, 256, SMEM1>>>(w1p, b_d1);   // h2 -> h1 (=h3)

    k_lang<<<NB, 64>>>(action, w_a1, b_a1, w_a2, b_a2);
    k_motion<<<(NB * NPIX) / 256, 256>>>(b_out, b_k, log_belief);
    k_gather<<<(NB * NPIX) / 256, 256>>>(out);
}

// round 6
// speedup vs baseline: 1.5562x; 1.5562x over previous
#include <cuda_runtime.h>
#include <cuda_bf16.h>
#include <math.h>

#define NB   8
#define DC   32
#define HS   512
#define WSZ  512
#define HH   256
#define WW   256
#define KW   7
#define KK2  49
#define HID  64
#define AA   256
#define NPIX 65536          // HH*WW
#define PADW 262
#define PPIX (PADW*PADW)    // 68644

typedef unsigned long long ull;

// ---------------- scratch (device globals; no runtime alloc) ----------------
__device__ __align__(256) float g_x  [NB * DC  * NPIX];
__device__ __align__(256) float g_u  [NB * KK2 * NPIX];
__device__ __align__(256) float g_sc [NB * NPIX];
__device__ __align__(256) float g_lang[NB * KK2];
__device__ __align__(256) float g_h1 [(size_t)NB * NPIX * HID];  // h3 rows [pix][ic]

// transposed zero-padded activations: [n][pixpad][128] bf16 (cols 0-63 hi, 64-127 lo)
__device__ __align__(256) __nv_bfloat16 g_t0[(size_t)NB * PPIX * 128];
__device__ __align__(256) __nv_bfloat16 g_t1[(size_t)NB * PPIX * 128];

// conv weights merged: [tap][oc][128] (cols 0-63 Wh over ic, 64-127 Wl)
__device__ __align__(256) __nv_bfloat16 g_w3m[9 * 64 * 128];
__device__ __align__(256) __nv_bfloat16 g_w1m[9 * 64 * 128];

// packed f32x2 weights for pointwise kernels
__device__ __align__(16) ull g_wi[DC * 32];
__device__ __align__(16) ull g_wo[HID * 16];
__device__ __align__(16) ull g_wk[DC * 25];

// ---------------- f32x2 helpers -------------------------------------------
__device__ __forceinline__ ull pack2(float lo, float hi) {
    ull r; asm("mov.b64 %0, {%1, %2};" : "=l"(r) : "f"(lo), "f"(hi)); return r;
}
__device__ __forceinline__ void unpack2(ull v, float& lo, float& hi) {
    asm("mov.b64 {%0, %1}, %2;" : "=f"(lo), "=f"(hi) : "l"(v));
}
__device__ __forceinline__ void ffma2(ull& d, ull a, ull b) {
    asm("fma.rn.f32x2 %0, %1, %2, %0;" : "+l"(d) : "l"(a), "l"(b));
}
__device__ __forceinline__ float fexp(float x) {
    float t  = fmaxf(x * 1.44269504f, -120.f);
    float rv = rintf(t);
    int   e  = (int)rv;
    float f  = t - rv;
    float p  = 1.33335581e-3f;
    p = fmaf(p, f, 9.61812910e-3f);
    p = fmaf(p, f, 5.55041087e-2f);
    p = fmaf(p, f, 2.40226507e-1f);
    p = fmaf(p, f, 6.93147181e-1f);
    p = fmaf(p, f, 1.0f);
    return __int_as_float(__float_as_int(p) + (e << 23));
}

// ---------------- tensor-core helpers (sm_80 baseline features) ------------
__device__ __forceinline__ unsigned smem_u32(const void* p) {
    unsigned a;
    asm("{ .reg .u64 t; cvta.to.shared.u64 t, %1; cvt.u32.u64 %0, t; }"
        : "=r"(a) : "l"(p));
    return a;
}
__device__ __forceinline__ void ldsm4(unsigned& r0, unsigned& r1,
                                      unsigned& r2, unsigned& r3, unsigned addr) {
    asm volatile("ldmatrix.sync.aligned.m8n8.x4.shared.b16 {%0,%1,%2,%3}, [%4];"
                 : "=r"(r0), "=r"(r1), "=r"(r2), "=r"(r3) : "r"(addr));
}
__device__ __forceinline__ void mma16816(float* c, const unsigned* a,
                                         unsigned b0, unsigned b1) {
    asm volatile(
        "mma.sync.aligned.m16n8k16.row.col.f32.bf16.bf16.f32 "
        "{%0,%1,%2,%3}, {%4,%5,%6,%7}, {%8,%9}, {%0,%1,%2,%3};"
        : "+f"(c[0]), "+f"(c[1]), "+f"(c[2]), "+f"(c[3])
        : "r"(a[0]), "r"(a[1]), "r"(a[2]), "r"(a[3]), "r"(b0), "r"(b1));
}

// ---------------- K0: pre-pack all weights --------------------------------
__global__ void k_prepw(const float* __restrict__ w_d3, const float* __restrict__ w_d1,
                        const float* __restrict__ w_in, const float* __restrict__ w_out,
                        const float* __restrict__ w_k) {
    int i = blockIdx.x * 256 + threadIdx.x;
    if (i < 73728) {
        int c = i & 127, oc = (i >> 7) & 63, tap = i >> 13;
        int ic = c & 63;
        float w = w_d3[((size_t)oc * HID + ic) * 9 + tap];
        __nv_bfloat16 h = __float2bfloat16_rn(w);
        g_w3m[i] = (c < 64) ? h : __float2bfloat16_rn(w - __bfloat162float(h));
    } else if (i < 147456) {
        int q = i - 73728;
        int c = q & 127, oc = (q >> 7) & 63, tap = q >> 13;
        int ic = c & 63;
        float w = w_d1[((size_t)oc * HID + ic) * 9 + tap];
        __nv_bfloat16 h = __float2bfloat16_rn(w);
        g_w1m[q] = (c < 64) ? h : __float2bfloat16_rn(w - __bfloat162float(h));
    } else if (i < 148480) {
        int q = i - 147456; int c = q >> 5, j = q & 31;
        g_wi[q] = pack2(w_in[(2*j)*DC + c], w_in[(2*j+1)*DC + c]);
    } else if (i < 149504) {
        int q = i - 148480; int ic = q >> 4, cc = q & 15;
        g_wo[q] = pack2(w_out[(2*cc)*HID + ic], w_out[(2*cc+1)*HID + ic]);
    } else if (i < 150304) {
        int q = i - 149504; int c = q / 25, kk = q % 25;
        float w1v = (2*kk + 1 < KK2) ? w_k[(2*kk+1)*DC + c] : 0.f;
        g_wk[q] = pack2(w_k[(2*kk)*DC + c], w1v);
    }
}

// ---------------- K0b: zero pad borders of transposed buffers --------------
__global__ void k_border() {
    int i = blockIdx.x * 256 + threadIdx.x;   // over NB*PPIX
    if (i >= NB * PPIX) return;
    int p = i % PPIX;
    int y = p / PADW, x = p % PADW;
    if (y >= 3 && y < 259 && x >= 3 && x < 259) return;
    size_t row = (size_t)i * 128;
    uint4 z = make_uint4(0, 0, 0, 0);
#pragma unroll
    for (int c = 0; c < 16; c++) {
        ((uint4*)(g_t0 + row))[c] = z;
        ((uint4*)(g_t1 + row))[c] = z;
    }
}

// ---------------- K1: 2x2 max pool ----------------------------------------
__global__ void k_maxpool(const float* __restrict__ sem) {
    int idx = blockIdx.x * blockDim.x + threadIdx.x;
    int x  = idx & (WW - 1);
    int y  = (idx >> 8) & (HH - 1);
    int nc = idx >> 16;
    const float* base = sem + (size_t)nc * HS * WSZ;
    const float2* r0 = (const float2*)(base + (size_t)(2 * y)     * WSZ);
    const float2* r1 = (const float2*)(base + (size_t)(2 * y + 1) * WSZ);
    float2 a = r0[x];
    float2 b = r1[x];
    g_x[idx] = fmaxf(fmaxf(a.x, a.y), fmaxf(b.x, b.y));
}

// ---------------- K2: conv1x1 32->64 + relu -> merged bf16 rows ------------
__global__ __launch_bounds__(256) void k_conv_in(const float* __restrict__ b) {
    __shared__ ull   sw2[DC * 32];
    __shared__ float sb[HID];
    for (int i = threadIdx.x; i < DC * 32; i += 256) sw2[i] = g_wi[i];
    if (threadIdx.x < HID) sb[threadIdx.x] = b[threadIdx.x];
    __syncthreads();

    int p   = blockIdx.x * 256 + threadIdx.x;
    int n   = p >> 16;
    int pix = p & (NPIX - 1);

    ull acc[32];
#pragma unroll
    for (int j = 0; j < 32; j++) acc[j] = pack2(sb[2*j], sb[2*j+1]);

    const float* xb = g_x + (size_t)n * DC * NPIX + pix;
#pragma unroll
    for (int c = 0; c < DC; c++) {
        float xv = xb[(size_t)c * NPIX];
        ull xp = pack2(xv, xv);
#pragma unroll
        for (int j = 0; j < 32; j++) ffma2(acc[j], sw2[c*32 + j], xp);
    }

    unsigned hi[32], lo2[32];
#pragma unroll
    for (int j = 0; j < 32; j++) {
        float v0, v1; unpack2(acc[j], v0, v1);
        v0 = fmaxf(v0, 0.f); v1 = fmaxf(v1, 0.f);
        __nv_bfloat162 bh = __floats2bfloat162_rn(v0, v1);
        float q0 = v0 - __bfloat162float(__low2bfloat16(bh));
        float q1 = v1 - __bfloat162float(__high2bfloat16(bh));
        __nv_bfloat162 bl = __floats2bfloat162_rn(q0, q1);
        hi[j]  = *(unsigned*)&bh;
        lo2[j] = *(unsigned*)&bl;
    }

    int y = pix >> 8, x = pix & 255;
    uint4* d4 = (uint4*)(g_t0 + ((size_t)n * PPIX + (size_t)(y + 3) * PADW + (x + 3)) * 128);
#pragma unroll
    for (int q = 0; q < 8; q++)
        d4[q] = make_uint4(hi[4*q], hi[4*q+1], hi[4*q+2], hi[4*q+3]);
#pragma unroll
    for (int q = 0; q < 8; q++)
        d4[8+q] = make_uint4(lo2[4*q], lo2[4*q+1], lo2[4*q+2], lo2[4*q+3]);
}

// ---------------- K3/K4: conv3x3 via mma.sync (split-bf16, 3 products) -----
// CTA = one output row (256 px), N=64 oc. 8 warps 4x2: warp = 64 px x 32 oc.
// SMEM: [0, 67072) A row buffer (262 px x 256B, swizzled)
//       [67072, 83456) W tap buffer (64 oc x 256B, swizzled)
//       [83456, 83712) bias
//       dump region aliases A ([0, 66560))
#define CSM_W   67072
#define CSM_B   83456
#define CSMEM   83712

template <int DIL, bool FIRST>
__global__ __launch_bounds__(256, 2) void k_convbf(const float* __restrict__ bg) {
    constexpr int NSP = 256 + 2 * DIL;
    const __nv_bfloat16* tin = FIRST ? g_t0  : g_t1;
    const __nv_bfloat16* wgt = FIRST ? g_w3m : g_w1m;

    extern __shared__ char smem[];
    unsigned sbase = smem_u32(smem);
    unsigned Wb = sbase + CSM_W;
    float* sbias = (float*)(smem + CSM_B);

    int tid = threadIdx.x, lane = tid & 31, w = tid >> 5;
    int wm = w & 3, wn = w >> 2;
    int y = blockIdx.x, n = blockIdx.y;
    if (tid < 64) sbias[tid] = bg[tid];

    float acc[4][4][4];
#pragma unroll
    for (int a = 0; a < 4; a++)
#pragma unroll
        for (int b = 0; b < 4; b++)
#pragma unroll
            for (int c = 0; c < 4; c++) acc[a][b][c] = 0.f;

    const size_t nb = (size_t)n * PPIX;
    const int akoff = ((lane >> 4) & 1) << 4;
    const int bkoff = ((lane >> 3) & 1) << 4;

    for (int ky = 0; ky < 3; ky++) {
        __syncthreads();
        {   // stage input row (all 3 kx share it)
            int ypad = y + (ky - 1) * DIL + 3;
            const __nv_bfloat16* src = tin + (nb + (size_t)ypad * PADW + (3 - DIL)) * 128;
            for (int i = tid; i < NSP * 16; i += 256) {
                int sp = i >> 4, seg = i & 15;
                unsigned rel = sp * 256 + ((seg << 4) ^ ((sp & 7) << 4));
                *(uint4*)(smem + rel) = *(const uint4*)(src + sp * 128 + seg * 8);
            }
        }
        for (int kx = 0; kx < 3; kx++) {
            __syncthreads();
            {   // stage weight tap
                const __nv_bfloat16* ws = wgt + (size_t)(ky * 3 + kx) * 64 * 128;
                for (int i = tid; i < 1024; i += 256) {
                    int oc = i >> 4, seg = i & 15;
                    unsigned rel = oc * 256 + ((seg << 4) ^ ((oc & 7) << 4));
                    *(uint4*)(smem + CSM_W + rel) = *(const uint4*)(ws + oc * 128 + seg * 8);
                }
            }
            __syncthreads();

            unsigned arow[4], arx[4];
#pragma unroll
            for (int mt = 0; mt < 4; mt++) {
                int px = wm * 64 + mt * 16 + ((lane >> 3) & 1) * 8 + (lane & 7);
                int sp = px + kx * DIL;
                arow[mt] = sbase + sp * 256;
                arx[mt]  = (sp & 7) << 4;
            }
            unsigned brow[2], brx[2];
#pragma unroll
            for (int nb2 = 0; nb2 < 2; nb2++) {
                int oc = wn * 32 + nb2 * 16 + ((lane >> 4) & 1) * 8 + (lane & 7);
                brow[nb2] = Wb + oc * 256;
                brx[nb2]  = (oc & 7) << 4;
            }

#pragma unroll
            for (int prod = 0; prod < 3; prod++) {
                int kA = (prod == 2) ? 128 : 0;   // byte offset: lo half of A
                int kW = (prod == 1) ? 128 : 0;   // byte offset: lo half of W
#pragma unroll
                for (int kc = 0; kc < 4; kc++) {
                    unsigned a[4][4];
#pragma unroll
                    for (int mt = 0; mt < 4; mt++)
                        ldsm4(a[mt][0], a[mt][1], a[mt][2], a[mt][3],
                              arow[mt] + (unsigned)((kA + kc * 32 + akoff) ^ arx[mt]));
                    unsigned b[2][4];
#pragma unroll
                    for (int nb2 = 0; nb2 < 2; nb2++)
                        ldsm4(b[nb2][0], b[nb2][1], b[nb2][2], b[nb2][3],
                              brow[nb2] + (unsigned)((kW + kc * 32 + bkoff) ^ brx[nb2]));
#pragma unroll
                    for (int mt = 0; mt < 4; mt++)
#pragma unroll
                        for (int nt = 0; nt < 4; nt++)
                            mma16816(acc[mt][nt], a[mt],
                                     b[nt >> 1][(nt & 1) * 2],
                                     b[nt >> 1][(nt & 1) * 2 + 1]);
                }
            }
        }
    }

    // ------- epilogue: dump accs to smem [px][65] f32, then row writes -------
    __syncthreads();
    float* sd = (float*)smem;
#pragma unroll
    for (int mt = 0; mt < 4; mt++)
#pragma unroll
        for (int nt = 0; nt < 4; nt++)
#pragma unroll
            for (int c = 0; c < 4; c++) {
                int px = wm * 64 + mt * 16 + (lane >> 2) + ((c >> 1) & 1) * 8;
                int oc = wn * 32 + nt * 8 + 2 * (lane & 3) + (c & 1);
                sd[px * 65 + oc] = acc[mt][nt][c];
            }
    __syncthreads();

    {
        int px = tid;
        const float* r = sd + px * 65;
        if (FIRST) {
            unsigned hi[32], lo2[32];
#pragma unroll
            for (int j = 0; j < 32; j++) {
                float v0 = fmaxf(r[2*j]   + sbias[2*j],   0.f);
                float v1 = fmaxf(r[2*j+1] + sbias[2*j+1], 0.f);
                __nv_bfloat162 bh = __floats2bfloat162_rn(v0, v1);
                float q0 = v0 - __bfloat162float(__low2bfloat16(bh));
                float q1 = v1 - __bfloat162float(__high2bfloat16(bh));
                __nv_bfloat162 bl = __floats2bfloat162_rn(q0, q1);
                hi[j]  = *(unsigned*)&bh;
                lo2[j] = *(unsigned*)&bl;
            }
            uint4* d4 = (uint4*)(g_t1 + (nb + (size_t)(y + 3) * PADW + (px + 3)) * 128);
#pragma unroll
            for (int q = 0; q < 8; q++)
                d4[q] = make_uint4(hi[4*q], hi[4*q+1], hi[4*q+2], hi[4*q+3]);
#pragma unroll
            for (int q = 0; q < 8; q++)
                d4[8+q] = make_uint4(lo2[4*q], lo2[4*q+1], lo2[4*q+2], lo2[4*q+3]);
        } else {
            float4* d4 = (float4*)(g_h1 + ((size_t)n * NPIX + y * WW + px) * HID);
#pragma unroll
            for (int q = 0; q < 16; q++)
                d4[q] = make_float4(fmaxf(r[4*q]   + sbias[4*q],   0.f),
                                    fmaxf(r[4*q+1] + sbias[4*q+1], 0.f),
                                    fmaxf(r[4*q+2] + sbias[4*q+2], 0.f),
                                    fmaxf(r[4*q+3] + sbias[4*q+3], 0.f));
        }
    }
}

// ---------------- K5: lang = log_softmax(relu(a@w1+b1)@w2+b2) -------------
__global__ void k_lang(const float* __restrict__ act,
                       const float* __restrict__ w1, const float* __restrict__ b1,
                       const float* __restrict__ w2, const float* __restrict__ b2) {
    int n = blockIdx.x;
    int t = threadIdx.x;      // 64 threads
    __shared__ float sh[HID];
    __shared__ float sz[KK2];
    __shared__ float slse;

    float acc = b1[t];
    for (int i = 0; i < AA; i++) acc = fmaf(act[n * AA + i], w1[i * HID + t], acc);
    sh[t] = fmaxf(acc, 0.f);
    __syncthreads();

    if (t < KK2) {
        float z = b2[t];
        for (int j = 0; j < HID; j++) z = fmaf(sh[j], w2[j * KK2 + t], z);
        sz[t] = z;
    }
    __syncthreads();
    if (t == 0) {
        float m = -1e30f;
        for (int k = 0; k < KK2; k++) m = fmaxf(m, sz[k]);
        float s = 0.f;
        for (int k = 0; k < KK2; k++) s += __expf(sz[k] - m);
        slse = m + __logf(s);
    }
    __syncthreads();
    if (t < KK2) g_lang[n * KK2 + t] = sz[t] - slse;
}

// ---- K6: fused  x2 = x + conv1x1(h3) ; z = w_k*x2 + b_k + lang ;
//          u = exp(z - m) streamed, scale = exp(lb)/sum(u) -----------------
__global__ __launch_bounds__(256) void k_motion(const float* __restrict__ b_out,
                                                const float* __restrict__ b_k,
                                                const float* __restrict__ lb) {
    __shared__ ull   swo2[HID * 16];
    __shared__ ull   swk2[DC * 25];
    __shared__ float sbo[DC];
    __shared__ float sbk[KK2];
    for (int i = threadIdx.x; i < HID * 16; i += 256) swo2[i] = g_wo[i];
    for (int i = threadIdx.x; i < DC * 25;  i += 256) swk2[i] = g_wk[i];
    if (threadIdx.x < DC)  sbo[threadIdx.x] = b_out[threadIdx.x];
    if (threadIdx.x < KK2) sbk[threadIdx.x] = b_k[threadIdx.x];
    __syncthreads();

    int p   = blockIdx.x * 256 + threadIdx.x;
    int n   = p >> 16;
    int pix = p & (NPIX - 1);

    ull x22[16];
    const float* xb = g_x + (size_t)n * DC * NPIX + pix;
#pragma unroll
    for (int cc = 0; cc < 16; cc++)
        x22[cc] = pack2(xb[(size_t)(2*cc)*NPIX]   + sbo[2*cc],
                        xb[(size_t)(2*cc+1)*NPIX] + sbo[2*cc+1]);

    const float4* hb4 = (const float4*)(g_h1 + (size_t)p * HID);   // h3 row
#pragma unroll 4
    for (int ic4 = 0; ic4 < 16; ic4++) {
        float4 h4 = hb4[ic4];
#pragma unroll
        for (int j = 0; j < 4; j++) {
            float hv = (&h4.x)[j];
            ull hp = pack2(hv, hv);
            int ic = ic4 * 4 + j;
#pragma unroll
            for (int cc = 0; cc < 16; cc++) ffma2(x22[cc], swo2[ic*16 + cc], hp);
        }
    }

    const float* lg = g_lang + n * KK2;
    ull z2[25];
#pragma unroll
    for (int kk = 0; kk < 24; kk++)
        z2[kk] = pack2(sbk[2*kk]   + __ldg(&lg[2*kk]),
                       sbk[2*kk+1] + __ldg(&lg[2*kk+1]));
    z2[24] = pack2(sbk[48] + __ldg(&lg[48]), -1e4f);

#pragma unroll
    for (int cc = 0; cc < 16; cc++) {
        float x0, x1; unpack2(x22[cc], x0, x1);
        ull xp0 = pack2(x0, x0);
#pragma unroll
        for (int kk = 0; kk < 25; kk++) ffma2(z2[kk], swk2[(2*cc)*25 + kk], xp0);
        ull xp1 = pack2(x1, x1);
#pragma unroll
        for (int kk = 0; kk < 25; kk++) ffma2(z2[kk], swk2[(2*cc+1)*25 + kk], xp1);
    }

    float m = -1e30f;
#pragma unroll
    for (int kk = 0; kk < 25; kk++) {
        float a, b2v; unpack2(z2[kk], a, b2v);
        m = fmaxf(m, fmaxf(a, b2v));
    }

    float s = 0.f;
    float* ubp = g_u + (size_t)n * KK2 * NPIX + pix;
#pragma unroll
    for (int kk = 0; kk < 25; kk++) {
        float a, b2v; unpack2(z2[kk], a, b2v);
        float ua = fexp(a - m);
        s += ua;
        ubp[(size_t)(2*kk) * NPIX] = ua;
        if (kk < 24) {
            float ubv = fexp(b2v - m);
            s += ubv;
            ubp[(size_t)(2*kk+1) * NPIX] = ubv;
        }
    }
    g_sc[p] = __fdividef(fexp(lb[p]), s);
}

// ---------------- K7: gather logsumexp (exp domain) ------------------------
__global__ __launch_bounds__(256) void k_gather(float* __restrict__ out) {
    int p   = blockIdx.x * 256 + threadIdx.x;
    int n   = p >> 16;
    int pix = p & (NPIX - 1);
    int y = pix >> 8;
    int x = pix & (WW - 1);

    const float* ub = g_u  + (size_t)n * KK2 * NPIX;
    const float* sc = g_sc + (size_t)n * NPIX;
    float s = 0.f;
#pragma unroll
    for (int ki = 0; ki < KW; ki++) {
        int h = y - ki + 3;
        if (h < 0 || h >= HH) continue;
        int rb = h * WW;
#pragma unroll
        for (int kj = 0; kj < KW; kj++) {
            int w = x - kj + 3;
            if (w < 0 || w >= WW) continue;
            int kk = ki * KW + kj;
            s = fmaf(ub[(size_t)kk * NPIX + rb + w], sc[rb + w], s);
        }
    }
    out[p] = __logf(s);
}

// ---------------- launch ---------------------------------------------------
extern "C" void kernel_launch(void* const* d_in, const int* in_sizes, int n_in,
                              void* d_out, int out_size) {
    const float* log_belief = (const float*)d_in[0];
    const float* semantic   = (const float*)d_in[1];
    const float* action     = (const float*)d_in[2];
    const float* w_in  = (const float*)d_in[3];
    const float* b_in  = (const float*)d_in[4];
    const float* w_d3  = (const float*)d_in[5];
    const float* b_d3  = (const float*)d_in[6];
    const float* w_d1  = (const float*)d_in[7];
    const float* b_d1  = (const float*)d_in[8];
    const float* w_out = (const float*)d_in[9];
    const float* b_out = (const float*)d_in[10];
    const float* w_k   = (const float*)d_in[11];
    const float* b_k   = (const float*)d_in[12];
    const float* w_a1  = (const float*)d_in[13];
    const float* b_a1  = (const float*)d_in[14];
    const float* w_a2  = (const float*)d_in[15];
    const float* b_a2  = (const float*)d_in[16];
    float* out = (float*)d_out;

    cudaFuncSetAttribute(k_convbf<3, true>,
                         cudaFuncAttributeMaxDynamicSharedMemorySize, CSMEM);
    cudaFuncSetAttribute(k_convbf<1, false>,
                         cudaFuncAttributeMaxDynamicSharedMemorySize, CSMEM);

    k_prepw<<<(150304 + 255) / 256, 256>>>(w_d3, w_d1, w_in, w_out, w_k);
    k_border<<<(NB * PPIX + 255) / 256, 256>>>();
    k_maxpool<<<(NB * DC * NPIX) / 256, 256>>>(semantic);
    k_conv_in<<<(NB * NPIX) / 256, 256>>>(b_in);

    dim3 cgrid(HH, NB);
    k_convbf<3, true ><<<cgrid, 256, CSMEM>>>(b_d3);   // t0 -> t1
    k_convbf<1, false><<<cgrid, 256, CSMEM>>>(b_d1);   // t1 -> h3 rows

    k_lang<<<NB, 64>>>(action, w_a1, b_a1, w_a2, b_a2);
    k_motion<<<(NB * NPIX) / 256, 256>>>(b_out, b_k, log_belief);
    k_gather<<<(NB * NPIX) / 256, 256>>>(out);
}